// round 1
// baseline (speedup 1.0000x reference)
#include <cuda_runtime.h>

// HyperComplexAdapterBlock: y = phm_up(gelu_new(phm_down(x)))
// PHM with rank-1 factors:
//   down: s[a][i] = sum_p x[a*192+p]*Ld[i*192+p]
//         t[c][i] = sum_a rule_d[i*16+a*4+c]*s[a][i]
//         z[c*48+q] = bd[c*48+q] + sum_i t[c][i]*Rd[i*48+q]
//   gelu_new(z), then symmetric up (p=48, q=192).
//
// One warp per token. Coalesced global I/O, transpose via skewed smem stage
// (slot(h) = h + h/6) so lane l owns contiguous elements 24l..24l+23
// (single a-group a = l>>3). Group-of-8 butterfly reductions (12 SHFL) +
// 16 broadcast SHFLs per projection. Weights in smem, rules/bias_d in regs.

#define WARPS 8
#define NTHREADS 256
#define STAGE_SLOTS 224

__global__ __launch_bounds__(NTHREADS, 2)
void phm_fused_kernel(const float* __restrict__ x,
                      const float* __restrict__ rule_d,
                      const float* __restrict__ Ld,
                      const float* __restrict__ Rd,
                      const float* __restrict__ bd,
                      const float* __restrict__ rule_u,
                      const float* __restrict__ Lu,
                      const float* __restrict__ Ru,
                      const float* __restrict__ bu,
                      float* __restrict__ out,
                      int ntok)
{
    __shared__ float sLd[768];
    __shared__ float sRd[192];
    __shared__ float sLu[192];
    __shared__ float sRu[768];
    __shared__ float sBu[768];
    __shared__ float4 stg[WARPS][STAGE_SLOTS];

    const int tid = threadIdx.x;
    for (int k = tid; k < 768; k += NTHREADS) {
        sLd[k] = Ld[k];
        sRu[k] = Ru[k];
        sBu[k] = bu[k];
    }
    for (int k = tid; k < 192; k += NTHREADS) {
        sRd[k] = Rd[k];
        sLu[k] = Lu[k];
    }
    __syncthreads();

    const int l  = tid & 31;
    const int w  = tid >> 5;
    const int c  = l >> 3;         // group (a on input side, c on output side)
    const int q8 = (l & 7) * 6;    // base offset within the group

    // token-invariant per-lane constants
    float ruleD[16], ruleU[16], biasD[6];
#pragma unroll
    for (int a = 0; a < 4; a++)
#pragma unroll
        for (int i = 0; i < 4; i++) {
            ruleD[a*4 + i] = rule_d[i*16 + a*4 + c];
            ruleU[a*4 + i] = rule_u[i*16 + a*4 + c];
        }
#pragma unroll
    for (int j = 0; j < 6; j++)
        biasD[j] = bd[c*48 + q8 + j];

    int wslot[6];
#pragma unroll
    for (int j = 0; j < 6; j++) { int f = l + 32*j; wslot[j] = f + f/6; }
    const int r0 = 7 * l;  // rslot[j] = r0 + j  (== slot(6l+j))

    const float4* x4   = (const float4*)x;
    float4*       o4   = (float4*)out;
    const float4* sLd4 = (const float4*)sLd;
    const float4* sRu4 = (const float4*)sRu;
    const float4* sBu4 = (const float4*)sBu;

    const int gw = blockIdx.x * WARPS + w;
    const int nw = gridDim.x * WARPS;

    for (int tok = gw; tok < ntok; tok += nw) {
        const float4* xr = x4 + (size_t)tok * 192;

        __syncwarp();  // prior iter's out-stage reads done before overwrite
#pragma unroll
        for (int j = 0; j < 6; j++)
            stg[w][wslot[j]] = xr[l + 32*j];   // coalesced LDG.128 -> skewed STS
        __syncwarp();

        float4 u[6];
#pragma unroll
        for (int j = 0; j < 6; j++)
            u[j] = stg[w][r0 + j];             // conflict-free LDS.128

        // ---- down: s[a][i] partials over lane's 24 contiguous elems ----
        float si[4];
#pragma unroll
        for (int i = 0; i < 4; i++) {
            float acc = 0.f;
#pragma unroll
            for (int j = 0; j < 6; j++) {
                float4 wv = sLd4[i*48 + q8 + j];
                acc = fmaf(u[j].x, wv.x, acc);
                acc = fmaf(u[j].y, wv.y, acc);
                acc = fmaf(u[j].z, wv.z, acc);
                acc = fmaf(u[j].w, wv.w, acc);
            }
            si[i] = acc;
        }
        // reduce within the 8-lane a-group
#pragma unroll
        for (int i = 0; i < 4; i++) {
            si[i] += __shfl_xor_sync(0xffffffffu, si[i], 4);
            si[i] += __shfl_xor_sync(0xffffffffu, si[i], 2);
            si[i] += __shfl_xor_sync(0xffffffffu, si[i], 1);
        }
        // t[c][i] for this lane's c (broadcast s[a][i] from lane 8a)
        float tD[4] = {0.f, 0.f, 0.f, 0.f};
#pragma unroll
        for (int a = 0; a < 4; a++)
#pragma unroll
            for (int i = 0; i < 4; i++)
                tD[i] = fmaf(ruleD[a*4 + i],
                             __shfl_sync(0xffffffffu, si[i], a*8), tD[i]);

        // ---- z + gelu_new (lane owns z elems 6l..6l+5) ----
        float zg[6];
#pragma unroll
        for (int j = 0; j < 6; j++) {
            float zv = biasD[j];
#pragma unroll
            for (int i = 0; i < 4; i++)
                zv = fmaf(tD[i], sRd[i*48 + q8 + j], zv);
            float w3  = zv * zv * zv;
            float arg = 0.7978845608028654f * fmaf(0.044715f, w3, zv);
            // 0.5*z*(1+tanh(arg)) == z / (1 + exp(-2*arg))  (exact algebra)
            zg[j] = __fdividef(zv, 1.0f + __expf(-2.0f * arg));
        }

        // ---- up: s2[a][i] over lane's 6 z elems (a = l>>3 again) ----
        float s2[4];
#pragma unroll
        for (int i = 0; i < 4; i++) {
            float acc = 0.f;
#pragma unroll
            for (int j = 0; j < 6; j++)
                acc = fmaf(zg[j], sLu[i*48 + q8 + j], acc);
            s2[i] = acc;
        }
#pragma unroll
        for (int i = 0; i < 4; i++) {
            s2[i] += __shfl_xor_sync(0xffffffffu, s2[i], 4);
            s2[i] += __shfl_xor_sync(0xffffffffu, s2[i], 2);
            s2[i] += __shfl_xor_sync(0xffffffffu, s2[i], 1);
        }
        float tU[4] = {0.f, 0.f, 0.f, 0.f};
#pragma unroll
        for (int a = 0; a < 4; a++)
#pragma unroll
            for (int i = 0; i < 4; i++)
                tU[i] = fmaf(ruleU[a*4 + i],
                             __shfl_sync(0xffffffffu, s2[i], a*8), tU[i]);

        // ---- out: lane owns float4s h = 6l..6l+5; stage back for coalesced STG
        __syncwarp();  // x-stage reads done before overwriting stage
#pragma unroll
        for (int j = 0; j < 6; j++) {
            float4 o = sBu4[6*l + j];
#pragma unroll
            for (int i = 0; i < 4; i++) {
                float4 rv = sRu4[i*48 + q8 + j];
                o.x = fmaf(tU[i], rv.x, o.x);
                o.y = fmaf(tU[i], rv.y, o.y);
                o.z = fmaf(tU[i], rv.z, o.z);
                o.w = fmaf(tU[i], rv.w, o.w);
            }
            stg[w][r0 + j] = o;                // conflict-free STS.128
        }
        __syncwarp();

        float4* orow = o4 + (size_t)tok * 192;
#pragma unroll
        for (int j = 0; j < 6; j++)
            orow[l + 32*j] = stg[w][wslot[j]]; // skewed LDS -> coalesced STG.128
    }
}

extern "C" void kernel_launch(void* const* d_in, const int* in_sizes, int n_in,
                              void* d_out, int out_size)
{
    const float* x      = (const float*)d_in[0];
    const float* rule_d = (const float*)d_in[1];
    const float* Ld     = (const float*)d_in[2];
    const float* Rd     = (const float*)d_in[3];
    const float* bd     = (const float*)d_in[4];
    const float* rule_u = (const float*)d_in[5];
    const float* Lu     = (const float*)d_in[6];
    const float* Ru     = (const float*)d_in[7];
    const float* bu     = (const float*)d_in[8];

    const int ntok = in_sizes[0] / 768;

    // 296 blocks = 148 SMs * 2 CTAs (forced by __launch_bounds__(256,2)):
    // exactly one wave, grid-stride over tokens.
    phm_fused_kernel<<<296, NTHREADS>>>(x, rule_d, Ld, Rd, bd,
                                        rule_u, Lu, Ru, bu,
                                        (float*)d_out, ntok);
}

// round 2
// speedup vs baseline: 1.5772x; 1.5772x over previous
#include <cuda_runtime.h>

// HyperComplexAdapterBlock: y = phm_up(gelu_new(phm_down(x)))
// Rank-1 PHM:  down: s[a][i]=sum_p x[a*192+p]*Ld[i][p]
//              t[c][i]=sum_a rule_d[i,a,c]*s[a][i]
//              z[c*48+q]=bd[..]+sum_i t[c][i]*Rd[i][q]; gelu; symmetric up.
//
// R2: one warp processes TPI=4 tokens per iteration so every weight LDS is
// amortized over 4 tokens (weight LDS was the R1 bottleneck: L1=86%).
// All weight arrays repacked in smem with padded, per-8-lane-phase
// conflict-free layouts. Transposes via skewed smem stage (slot = f + f/6).

#define NW 4          // warps per CTA
#define NT 128        // threads per CTA
#define TPI 4         // tokens per warp-iteration
#define STF4 224      // padded stage slots (float4) per token

// byte offsets into dynamic smem
#define OFF_STG   0
#define SZ_STG    (NW * TPI * STF4 * 16)          // 57344
#define OFF_PLD   (OFF_STG + SZ_STG)              // [4][8][7] float4
#define OFF_PRU   (OFF_PLD + 4*8*7*16)            // [4][8][7] float4
#define OFF_PBU   (OFF_PRU + 4*8*7*16)            // [32][7]  float4
#define OFF_PRD   (OFF_PBU + 32*7*16)             // [4][8][12] float
#define OFF_PLU   (OFF_PRD + 4*8*12*4)            // [4][8][12] float
#define SMEM_TOTAL (OFF_PLU + 4*8*12*4)           // 71168 bytes

__global__ __launch_bounds__(NT, 3)
void phm_fused_kernel(const float* __restrict__ x,
                      const float* __restrict__ rule_d,
                      const float* __restrict__ Ld,
                      const float* __restrict__ Rd,
                      const float* __restrict__ bd,
                      const float* __restrict__ rule_u,
                      const float* __restrict__ Lu,
                      const float* __restrict__ Ru,
                      const float* __restrict__ bu,
                      float* __restrict__ out,
                      int ntok)
{
    extern __shared__ __align__(16) char smem[];
    float4* stg  = (float4*)(smem + OFF_STG);
    float4* pLd  = (float4*)(smem + OFF_PLD);
    float4* pRu  = (float4*)(smem + OFF_PRU);
    float4* pBu  = (float4*)(smem + OFF_PBU);
    float*  pRdS = (float*)(smem + OFF_PRD);
    float*  pLuS = (float*)(smem + OFF_PLU);

    const int tid = threadIdx.x;
    const float4* Ld4 = (const float4*)Ld;
    const float4* Ru4 = (const float4*)Ru;
    const float4* bu4 = (const float4*)bu;

    // repack weights into padded conflict-free layouts
    for (int idx = tid; idx < 4*8*6; idx += NT) {
        int i = idx / 48, r = idx % 48, kk = r / 6, j = r % 6;
        pLd [(i*8 + kk)*7  + j] = Ld4[i*48 + 6*kk + j];
        pRu [(i*8 + kk)*7  + j] = Ru4[i*48 + 6*kk + j];
        pRdS[(i*8 + kk)*12 + j] = Rd [i*48 + 6*kk + j];
        pLuS[(i*8 + kk)*12 + j] = Lu [i*48 + 6*kk + j];
    }
    for (int idx = tid; idx < 32*6; idx += NT) {
        int ll = idx / 6, j = idx % 6;
        pBu[ll*7 + j] = bu4[6*ll + j];
    }
    __syncthreads();

    const int l = tid & 31;
    const int w = tid >> 5;
    const int g = l >> 3;        // a-group on input side, c on output side
    const int k = l & 7;

    // token-invariant per-lane constants (registers)
    float ruleD[16], ruleU[16], biasD[6];
#pragma unroll
    for (int a = 0; a < 4; a++)
#pragma unroll
        for (int i = 0; i < 4; i++) {
            ruleD[a*4 + i] = rule_d[i*16 + a*4 + g];
            ruleU[a*4 + i] = rule_u[i*16 + a*4 + g];
        }
#pragma unroll
    for (int j = 0; j < 6; j++)
        biasD[j] = bd[6*l + j];

    int wslot[6];
#pragma unroll
    for (int j = 0; j < 6; j++) { int f = l + 32*j; wslot[j] = f + f/6; }
    const int r0 = 7 * l;        // read slot base (== slot(6l))

    const float4* x4 = (const float4*)x;
    float4*       o4 = (float4*)out;
    float4* stgW = stg + (size_t)w * (TPI * STF4);

    const int gwarp = blockIdx.x * NW + w;
    const int nwarp = gridDim.x * NW;

    for (int base = gwarp * TPI; base < ntok; base += nwarp * TPI) {
        // ---- stage in: 4 tokens, coalesced LDG.128 -> skewed STS ----
        __syncwarp();
#pragma unroll
        for (int tt = 0; tt < TPI; tt++) {
            int t = base + tt; if (t > ntok - 1) t = ntok - 1;
            const float4* xr = x4 + (size_t)t * 192;
#pragma unroll
            for (int j = 0; j < 6; j++)
                stgW[tt*STF4 + wslot[j]] = xr[l + 32*j];
        }
        __syncwarp();

        // ---- down stage 1: si[tt][i] partials, weights shared across 4 tok
        float si[TPI][4];
#pragma unroll
        for (int tt = 0; tt < TPI; tt++)
#pragma unroll
            for (int i = 0; i < 4; i++) si[tt][i] = 0.f;

#pragma unroll
        for (int j = 0; j < 6; j++) {
            float4 u[TPI];
#pragma unroll
            for (int tt = 0; tt < TPI; tt++)
                u[tt] = stgW[tt*STF4 + r0 + j];
#pragma unroll
            for (int i = 0; i < 4; i++) {
                float4 wv = pLd[(i*8 + k)*7 + j];
#pragma unroll
                for (int tt = 0; tt < TPI; tt++) {
                    si[tt][i] = fmaf(u[tt].x, wv.x, si[tt][i]);
                    si[tt][i] = fmaf(u[tt].y, wv.y, si[tt][i]);
                    si[tt][i] = fmaf(u[tt].z, wv.z, si[tt][i]);
                    si[tt][i] = fmaf(u[tt].w, wv.w, si[tt][i]);
                }
            }
        }
        // reduce within 8-lane a-groups
#pragma unroll
        for (int tt = 0; tt < TPI; tt++)
#pragma unroll
            for (int i = 0; i < 4; i++) {
                float v = si[tt][i];
                v += __shfl_xor_sync(0xffffffffu, v, 4);
                v += __shfl_xor_sync(0xffffffffu, v, 2);
                v += __shfl_xor_sync(0xffffffffu, v, 1);
                si[tt][i] = v;
            }

        // ---- down stage 2: t[c][i] ----
        float tD[TPI][4];
#pragma unroll
        for (int tt = 0; tt < TPI; tt++)
#pragma unroll
            for (int i = 0; i < 4; i++) tD[tt][i] = 0.f;
#pragma unroll
        for (int a = 0; a < 4; a++)
#pragma unroll
            for (int i = 0; i < 4; i++) {
                float r = ruleD[a*4 + i];
#pragma unroll
                for (int tt = 0; tt < TPI; tt++)
                    tD[tt][i] = fmaf(r, __shfl_sync(0xffffffffu, si[tt][i], a*8),
                                     tD[tt][i]);
            }

        // ---- fused z -> gelu_new -> up stage 1 (s2), weights shared ----
        float s2[TPI][4];
#pragma unroll
        for (int tt = 0; tt < TPI; tt++)
#pragma unroll
            for (int i = 0; i < 4; i++) s2[tt][i] = 0.f;

#pragma unroll
        for (int j = 0; j < 6; j++) {
            float zv[TPI];
#pragma unroll
            for (int tt = 0; tt < TPI; tt++) zv[tt] = biasD[j];
#pragma unroll
            for (int i = 0; i < 4; i++) {
                float rd = pRdS[(i*8 + k)*12 + j];
#pragma unroll
                for (int tt = 0; tt < TPI; tt++)
                    zv[tt] = fmaf(tD[tt][i], rd, zv[tt]);
            }
#pragma unroll
            for (int tt = 0; tt < TPI; tt++) {
                float z   = zv[tt];
                float arg = 0.7978845608028654f * fmaf(0.044715f*z, z*z, z);
                // 0.5*z*(1+tanh(arg)) == z / (1 + exp(-2*arg))
                zv[tt] = __fdividef(z, 1.0f + __expf(-2.0f * arg));
            }
#pragma unroll
            for (int i = 0; i < 4; i++) {
                float lu = pLuS[(i*8 + k)*12 + j];
#pragma unroll
                for (int tt = 0; tt < TPI; tt++)
                    s2[tt][i] = fmaf(zv[tt], lu, s2[tt][i]);
            }
        }
        // reduce s2 within 8-lane groups
#pragma unroll
        for (int tt = 0; tt < TPI; tt++)
#pragma unroll
            for (int i = 0; i < 4; i++) {
                float v = s2[tt][i];
                v += __shfl_xor_sync(0xffffffffu, v, 4);
                v += __shfl_xor_sync(0xffffffffu, v, 2);
                v += __shfl_xor_sync(0xffffffffu, v, 1);
                s2[tt][i] = v;
            }

        // ---- up stage 2: tU ----
        float tU[TPI][4];
#pragma unroll
        for (int tt = 0; tt < TPI; tt++)
#pragma unroll
            for (int i = 0; i < 4; i++) tU[tt][i] = 0.f;
#pragma unroll
        for (int a = 0; a < 4; a++)
#pragma unroll
            for (int i = 0; i < 4; i++) {
                float r = ruleU[a*4 + i];
#pragma unroll
                for (int tt = 0; tt < TPI; tt++)
                    tU[tt][i] = fmaf(r, __shfl_sync(0xffffffffu, s2[tt][i], a*8),
                                     tU[tt][i]);
            }

        // ---- up stage 3 + bias, stage out, coalesced STG.128 ----
        __syncwarp();
#pragma unroll
        for (int j = 0; j < 6; j++) {
            float4 bub = pBu[l*7 + j];
            float4 o[TPI];
#pragma unroll
            for (int tt = 0; tt < TPI; tt++) o[tt] = bub;
#pragma unroll
            for (int i = 0; i < 4; i++) {
                float4 rv = pRu[(i*8 + k)*7 + j];
#pragma unroll
                for (int tt = 0; tt < TPI; tt++) {
                    o[tt].x = fmaf(tU[tt][i], rv.x, o[tt].x);
                    o[tt].y = fmaf(tU[tt][i], rv.y, o[tt].y);
                    o[tt].z = fmaf(tU[tt][i], rv.z, o[tt].z);
                    o[tt].w = fmaf(tU[tt][i], rv.w, o[tt].w);
                }
            }
#pragma unroll
            for (int tt = 0; tt < TPI; tt++)
                stgW[tt*STF4 + r0 + j] = o[tt];
        }
        __syncwarp();
#pragma unroll
        for (int tt = 0; tt < TPI; tt++) {
            int t = base + tt;
            if (t < ntok) {
                float4* orow = o4 + (size_t)t * 192;
#pragma unroll
                for (int j = 0; j < 6; j++)
                    orow[l + 32*j] = stgW[tt*STF4 + wslot[j]];
            }
        }
    }
}

extern "C" void kernel_launch(void* const* d_in, const int* in_sizes, int n_in,
                              void* d_out, int out_size)
{
    const float* x      = (const float*)d_in[0];
    const float* rule_d = (const float*)d_in[1];
    const float* Ld     = (const float*)d_in[2];
    const float* Rd     = (const float*)d_in[3];
    const float* bd     = (const float*)d_in[4];
    const float* rule_u = (const float*)d_in[5];
    const float* Lu     = (const float*)d_in[6];
    const float* Ru     = (const float*)d_in[7];
    const float* bu     = (const float*)d_in[8];

    const int ntok = in_sizes[0] / 768;

    cudaFuncSetAttribute(phm_fused_kernel,
                         cudaFuncAttributeMaxDynamicSharedMemorySize,
                         SMEM_TOTAL);

    // 148 SMs * 3 CTAs (128 thr, 71KB smem each) = one full wave
    phm_fused_kernel<<<444, NT, SMEM_TOTAL>>>(x, rule_d, Ld, Rd, bd,
                                              rule_u, Lu, Ru, bu,
                                              (float*)d_out, ntok);
}

// round 3
// speedup vs baseline: 1.6355x; 1.0370x over previous
#include <cuda_runtime.h>

// HyperComplexAdapterBlock: y = phm_up(gelu_new(phm_down(x))), rank-1 PHM.
// R3: (a) direct coalesced output (no out-transpose stage): y_f computed from
//     shuffled tU + Ru read in coalesced layout; (b) stage transpose uses XOR
//     swizzle slot = f ^ ((f>>3)&1) (conflict-free both directions, no pad);
//     (c) 4 CTAs/SM (16 warps) via 128-thr blocks + 55.5KB smem.

#define NW 4          // warps per CTA
#define NT 128        // threads per CTA
#define TPI 4         // tokens per warp-iteration
#define SW(f) ((f) ^ (((f) >> 3) & 1))

// dynamic smem layout (bytes)
#define OFF_STG   0
#define SZ_STG    (NW * TPI * 192 * 16)           // 49152
#define OFF_PLD   (OFF_STG + SZ_STG)              // 192 float4, XOR-swizzled
#define OFF_PRU   (OFF_PLD + 3072)                // 192 float4, plain
#define OFF_PRD   (OFF_PRU + 3072)                // 192 float, plain
#define OFF_PLU   (OFF_PRD + 768)                 // 192 float, plain
#define SMEM_TOTAL (OFF_PLU + 768)                // 56832

__global__ __launch_bounds__(NT, 4)
void phm_fused_kernel(const float* __restrict__ x,
                      const float* __restrict__ rule_d,
                      const float* __restrict__ Ld,
                      const float* __restrict__ Rd,
                      const float* __restrict__ bd,
                      const float* __restrict__ rule_u,
                      const float* __restrict__ Lu,
                      const float* __restrict__ Ru,
                      const float* __restrict__ bu,
                      float* __restrict__ out,
                      int ntok)
{
    extern __shared__ __align__(16) char smem[];
    float4* stg  = (float4*)(smem + OFF_STG);
    float4* pLd  = (float4*)(smem + OFF_PLD);
    float4* pRu  = (float4*)(smem + OFF_PRU);
    float*  pRdS = (float*)(smem + OFF_PRD);
    float*  pLuS = (float*)(smem + OFF_PLU);

    const int tid = threadIdx.x;
    const float4* Ld4 = (const float4*)Ld;
    const float4* Ru4 = (const float4*)Ru;
    const float4* bu4 = (const float4*)bu;

    // weight repack: pLd XOR-swizzled (transposed-side reads), rest plain
    for (int idx = tid; idx < 192; idx += NT) {
        pLd [SW(idx)] = Ld4[idx];
        pRu [idx]     = Ru4[idx];
        pRdS[idx]     = Rd [idx];
        pLuS[idx]     = Lu [idx];
    }
    __syncthreads();

    const int l = tid & 31;
    const int w = tid >> 5;
    const int g = l >> 3;        // group: a on input side, c on z side
    const int k = l & 7;

    // token-invariant per-lane constants
    float ruleD[16], ruleU[16], biasD[6];
#pragma unroll
    for (int a = 0; a < 4; a++)
#pragma unroll
        for (int i = 0; i < 4; i++) {
            ruleD[a*4 + i] = rule_d[i*16 + a*4 + g];
            ruleU[a*4 + i] = rule_u[i*16 + a*4 + g];
        }
#pragma unroll
    for (int j = 0; j < 6; j++)
        biasD[j] = bd[6*l + j];

    int wsl[6], rsl[6], rwk[6];
#pragma unroll
    for (int j = 0; j < 6; j++) {
        wsl[j] = SW(l + 32*j);   // coalesced stage write
        rsl[j] = SW(6*l + j);    // transposed stage read
        rwk[6 > j ? j : 0] = SW(6*k + j);  // weight slice (per-k)
    }

    const float4* x4 = (const float4*)x;
    float4*       o4 = (float4*)out;
    float4* stgW = stg + (size_t)w * (TPI * 192);

    const int gwarp = blockIdx.x * NW + w;
    const int nwarp = gridDim.x * NW;

    for (int base = gwarp * TPI; base < ntok; base += nwarp * TPI) {
        // ---- stage in: TPI tokens, coalesced LDG.128 -> swizzled STS ----
        __syncwarp();
#pragma unroll
        for (int tt = 0; tt < TPI; tt++) {
            int t = base + tt; if (t > ntok - 1) t = ntok - 1;
            const float4* xr = x4 + (size_t)t * 192;
#pragma unroll
            for (int j = 0; j < 6; j++)
                stgW[tt*192 + wsl[j]] = xr[l + 32*j];
        }
        __syncwarp();

        // ---- down stage 1: si partials (weights shared across TPI) ----
        float si[TPI][4];
#pragma unroll
        for (int tt = 0; tt < TPI; tt++)
#pragma unroll
            for (int i = 0; i < 4; i++) si[tt][i] = 0.f;

#pragma unroll
        for (int j = 0; j < 6; j++) {
            float4 u[TPI];
#pragma unroll
            for (int tt = 0; tt < TPI; tt++)
                u[tt] = stgW[tt*192 + rsl[j]];
#pragma unroll
            for (int i = 0; i < 4; i++) {
                float4 wv = pLd[i*48 + rwk[j]];
#pragma unroll
                for (int tt = 0; tt < TPI; tt++) {
                    si[tt][i] = fmaf(u[tt].x, wv.x, si[tt][i]);
                    si[tt][i] = fmaf(u[tt].y, wv.y, si[tt][i]);
                    si[tt][i] = fmaf(u[tt].z, wv.z, si[tt][i]);
                    si[tt][i] = fmaf(u[tt].w, wv.w, si[tt][i]);
                }
            }
        }
#pragma unroll
        for (int tt = 0; tt < TPI; tt++)
#pragma unroll
            for (int i = 0; i < 4; i++) {
                float v = si[tt][i];
                v += __shfl_xor_sync(0xffffffffu, v, 4);
                v += __shfl_xor_sync(0xffffffffu, v, 2);
                v += __shfl_xor_sync(0xffffffffu, v, 1);
                si[tt][i] = v;
            }

        // ---- down stage 2: t[c][i] (c = g for this lane) ----
        float tD[TPI][4];
#pragma unroll
        for (int tt = 0; tt < TPI; tt++)
#pragma unroll
            for (int i = 0; i < 4; i++) tD[tt][i] = 0.f;
#pragma unroll
        for (int a = 0; a < 4; a++)
#pragma unroll
            for (int i = 0; i < 4; i++) {
                float r = ruleD[a*4 + i];
#pragma unroll
                for (int tt = 0; tt < TPI; tt++)
                    tD[tt][i] = fmaf(r, __shfl_sync(0xffffffffu, si[tt][i], a*8),
                                     tD[tt][i]);
            }

        // ---- fused z -> gelu_new -> up stage 1 (s2) ----
        float s2[TPI][4];
#pragma unroll
        for (int tt = 0; tt < TPI; tt++)
#pragma unroll
            for (int i = 0; i < 4; i++) s2[tt][i] = 0.f;

#pragma unroll
        for (int j = 0; j < 6; j++) {
            float zv[TPI];
#pragma unroll
            for (int tt = 0; tt < TPI; tt++) zv[tt] = biasD[j];
#pragma unroll
            for (int i = 0; i < 4; i++) {
                float rd = pRdS[i*48 + 6*k + j];
#pragma unroll
                for (int tt = 0; tt < TPI; tt++)
                    zv[tt] = fmaf(tD[tt][i], rd, zv[tt]);
            }
#pragma unroll
            for (int tt = 0; tt < TPI; tt++) {
                float z   = zv[tt];
                float arg = 0.7978845608028654f * fmaf(0.044715f*z, z*z, z);
                // 0.5*z*(1+tanh(arg)) == z / (1 + exp(-2*arg))
                zv[tt] = __fdividef(z, 1.0f + __expf(-2.0f * arg));
            }
#pragma unroll
            for (int i = 0; i < 4; i++) {
                float lu = pLuS[i*48 + 6*k + j];
#pragma unroll
                for (int tt = 0; tt < TPI; tt++)
                    s2[tt][i] = fmaf(zv[tt], lu, s2[tt][i]);
            }
        }
#pragma unroll
        for (int tt = 0; tt < TPI; tt++)
#pragma unroll
            for (int i = 0; i < 4; i++) {
                float v = s2[tt][i];
                v += __shfl_xor_sync(0xffffffffu, v, 4);
                v += __shfl_xor_sync(0xffffffffu, v, 2);
                v += __shfl_xor_sync(0xffffffffu, v, 1);
                s2[tt][i] = v;
            }

        // ---- up stage 2: tU[c][i] (c = g) ----
        float tU[TPI][4];
#pragma unroll
        for (int tt = 0; tt < TPI; tt++)
#pragma unroll
            for (int i = 0; i < 4; i++) tU[tt][i] = 0.f;
#pragma unroll
        for (int a = 0; a < 4; a++)
#pragma unroll
            for (int i = 0; i < 4; i++) {
                float r = ruleU[a*4 + i];
#pragma unroll
                for (int tt = 0; tt < TPI; tt++)
                    tU[tt][i] = fmaf(r, __shfl_sync(0xffffffffu, s2[tt][i], a*8),
                                     tU[tt][i]);
            }

        // ---- direct coalesced output: f = l + 32j, c = f/48 ----
#pragma unroll
        for (int j = 0; j < 6; j++) {
            const int f   = l + 32*j;
            const int c   = f / 48;
            const int src = c*8 + k;          // any lane of group c holds tU[c]
            const int q4  = f - c*48;
            float4 bb = __ldg(&bu4[f]);
            float4 rv[4];
#pragma unroll
            for (int i = 0; i < 4; i++) rv[i] = pRu[i*48 + q4];
#pragma unroll
            for (int tt = 0; tt < TPI; tt++) {
                float4 o = bb;
#pragma unroll
                for (int i = 0; i < 4; i++) {
                    float tv = __shfl_sync(0xffffffffu, tU[tt][i], src);
                    o.x = fmaf(tv, rv[i].x, o.x);
                    o.y = fmaf(tv, rv[i].y, o.y);
                    o.z = fmaf(tv, rv[i].z, o.z);
                    o.w = fmaf(tv, rv[i].w, o.w);
                }
                if (base + tt < ntok)
                    o4[(size_t)(base + tt) * 192 + f] = o;
            }
        }
    }
}

extern "C" void kernel_launch(void* const* d_in, const int* in_sizes, int n_in,
                              void* d_out, int out_size)
{
    const float* x      = (const float*)d_in[0];
    const float* rule_d = (const float*)d_in[1];
    const float* Ld     = (const float*)d_in[2];
    const float* Rd     = (const float*)d_in[3];
    const float* bd     = (const float*)d_in[4];
    const float* rule_u = (const float*)d_in[5];
    const float* Lu     = (const float*)d_in[6];
    const float* Ru     = (const float*)d_in[7];
    const float* bu     = (const float*)d_in[8];

    const int ntok = in_sizes[0] / 768;

    cudaFuncSetAttribute(phm_fused_kernel,
                         cudaFuncAttributeMaxDynamicSharedMemorySize,
                         SMEM_TOTAL);

    // 148 SMs * 4 CTAs (128 thr, 55.5KB smem each) = one full wave
    phm_fused_kernel<<<592, NT, SMEM_TOTAL>>>(x, rule_d, Ld, Rd, bd,
                                              rule_u, Lu, Ru, bu,
                                              (float*)d_out, ntok);
}

// round 4
// speedup vs baseline: 1.6861x; 1.0310x over previous
#include <cuda_runtime.h>

// HyperComplexAdapterBlock: y = phm_up(gelu_new(phm_down(x))), rank-1 PHM.
// R4: packed f32x2 FMA (fma.rn.f32x2) on the two 96-MAC/token stages;
//     TPI=3 + 5 CTAs/SM (20 warps) for latency hiding; rules in smem.

typedef unsigned long long u64;

__device__ __forceinline__ u64 fma2(u64 a, u64 b, u64 c) {
    u64 d;
    asm("fma.rn.f32x2 %0, %1, %2, %3;" : "=l"(d) : "l"(a), "l"(b), "l"(c));
    return d;
}
__device__ __forceinline__ u64 pk2(float lo, float hi) {
    u64 r; asm("mov.b64 %0, {%1, %2};" : "=l"(r) : "f"(lo), "f"(hi));
    return r;
}
__device__ __forceinline__ float sum2(u64 v) {
    float a, b; asm("mov.b64 {%0, %1}, %2;" : "=f"(a), "=f"(b) : "l"(v));
    return a + b;
}

#define NW 4          // warps per CTA
#define NT 128        // threads per CTA
#define TPI 3         // tokens per warp-iteration
#define SW(f) ((f) ^ (((f) >> 3) & 1))

// dynamic smem layout (bytes)
#define OFF_STG   0
#define SZ_STG    (NW * TPI * 192 * 16)           // 36864
#define OFF_PLD   (OFF_STG + SZ_STG)              // 192 f4, XOR-swizzled
#define OFF_PRU   (OFF_PLD + 3072)                // 192 f4, plain
#define OFF_PRD   (OFF_PRU + 3072)                // 192 f
#define OFF_PLU   (OFF_PRD + 768)                 // 192 f
#define OFF_RRD   (OFF_PLU + 768)                 // 64 f (rule_d)
#define OFF_RRU   (OFF_RRD + 256)                 // 64 f (rule_u)
#define SMEM_TOTAL (OFF_RRU + 256)                // 45056

__global__ __launch_bounds__(NT, 5)
void phm_fused_kernel(const float* __restrict__ x,
                      const float* __restrict__ rule_d,
                      const float* __restrict__ Ld,
                      const float* __restrict__ Rd,
                      const float* __restrict__ bd,
                      const float* __restrict__ rule_u,
                      const float* __restrict__ Lu,
                      const float* __restrict__ Ru,
                      const float* __restrict__ bu,
                      float* __restrict__ out,
                      int ntok)
{
    extern __shared__ __align__(16) char smem[];
    ulonglong2* stg  = (ulonglong2*)(smem + OFF_STG);
    ulonglong2* pLd2 = (ulonglong2*)(smem + OFF_PLD);
    ulonglong2* pRu2 = (ulonglong2*)(smem + OFF_PRU);
    float*      pRdS = (float*)(smem + OFF_PRD);
    float*      pLuS = (float*)(smem + OFF_PLU);
    float*      sRd  = (float*)(smem + OFF_RRD);
    float*      sRu  = (float*)(smem + OFF_RRU);

    const int tid = threadIdx.x;
    const ulonglong2* Ld2 = (const ulonglong2*)Ld;
    const ulonglong2* Ru2 = (const ulonglong2*)Ru;
    const ulonglong2* bu2 = (const ulonglong2*)bu;

    for (int idx = tid; idx < 192; idx += NT) {
        pLd2[SW(idx)] = Ld2[idx];
        pRu2[idx]     = Ru2[idx];
        pRdS[idx]     = Rd [idx];
        pLuS[idx]     = Lu [idx];
    }
    for (int idx = tid; idx < 64; idx += NT) {
        sRd[idx] = rule_d[idx];
        sRu[idx] = rule_u[idx];
    }
    __syncthreads();

    const int l = tid & 31;
    const int w = tid >> 5;
    const int g = l >> 3;        // group: a on input side, c on z side
    const int k = l & 7;

    float biasD[6];
#pragma unroll
    for (int j = 0; j < 6; j++)
        biasD[j] = bd[6*l + j];

    int wsl[6], rsl[6], rwk[6];
#pragma unroll
    for (int j = 0; j < 6; j++) {
        wsl[j] = SW(l + 32*j);   // coalesced stage write
        rsl[j] = SW(6*l + j);    // transposed stage read
        rwk[j] = SW(6*k + j);    // swizzled weight slice (per-k)
    }

    const ulonglong2* x2 = (const ulonglong2*)x;
    ulonglong2*       o2 = (ulonglong2*)out;
    ulonglong2* stgW = stg + (size_t)w * (TPI * 192);

    const int gwarp = blockIdx.x * NW + w;
    const int nwarp = gridDim.x * NW;

    for (int base = gwarp * TPI; base < ntok; base += nwarp * TPI) {
        // ---- stage in: TPI tokens, coalesced LDG.128 -> swizzled STS ----
        __syncwarp();
#pragma unroll
        for (int tt = 0; tt < TPI; tt++) {
            int t = base + tt; if (t > ntok - 1) t = ntok - 1;
            const ulonglong2* xr = x2 + (size_t)t * 192;
#pragma unroll
            for (int j = 0; j < 6; j++)
                stgW[tt*192 + wsl[j]] = xr[l + 32*j];
        }
        __syncwarp();

        // ---- down stage 1: si partials, packed f32x2 ----
        u64 si2[TPI][4];
#pragma unroll
        for (int tt = 0; tt < TPI; tt++)
#pragma unroll
            for (int i = 0; i < 4; i++) si2[tt][i] = 0ull;

#pragma unroll
        for (int j = 0; j < 6; j++) {
            ulonglong2 u[TPI];
#pragma unroll
            for (int tt = 0; tt < TPI; tt++)
                u[tt] = stgW[tt*192 + rsl[j]];
#pragma unroll
            for (int i = 0; i < 4; i++) {
                ulonglong2 wv = pLd2[i*48 + rwk[j]];
#pragma unroll
                for (int tt = 0; tt < TPI; tt++) {
                    si2[tt][i] = fma2(u[tt].x, wv.x, si2[tt][i]);
                    si2[tt][i] = fma2(u[tt].y, wv.y, si2[tt][i]);
                }
            }
        }
        float si[TPI][4];
#pragma unroll
        for (int tt = 0; tt < TPI; tt++)
#pragma unroll
            for (int i = 0; i < 4; i++) {
                float v = sum2(si2[tt][i]);
                v += __shfl_xor_sync(0xffffffffu, v, 4);
                v += __shfl_xor_sync(0xffffffffu, v, 2);
                v += __shfl_xor_sync(0xffffffffu, v, 1);
                si[tt][i] = v;
            }

        // ---- down stage 2: t[c][i] (c = g) ----
        float tD[TPI][4];
#pragma unroll
        for (int tt = 0; tt < TPI; tt++)
#pragma unroll
            for (int i = 0; i < 4; i++) tD[tt][i] = 0.f;
#pragma unroll
        for (int a = 0; a < 4; a++)
#pragma unroll
            for (int i = 0; i < 4; i++) {
                float r = sRd[i*16 + a*4 + g];
#pragma unroll
                for (int tt = 0; tt < TPI; tt++)
                    tD[tt][i] = fmaf(r, __shfl_sync(0xffffffffu, si[tt][i], a*8),
                                     tD[tt][i]);
            }

        // ---- fused z -> gelu_new -> up stage 1 (s2) ----
        float s2[TPI][4];
#pragma unroll
        for (int tt = 0; tt < TPI; tt++)
#pragma unroll
            for (int i = 0; i < 4; i++) s2[tt][i] = 0.f;

#pragma unroll
        for (int j = 0; j < 6; j++) {
            float zv[TPI];
#pragma unroll
            for (int tt = 0; tt < TPI; tt++) zv[tt] = biasD[j];
#pragma unroll
            for (int i = 0; i < 4; i++) {
                float rd = pRdS[i*48 + 6*k + j];
#pragma unroll
                for (int tt = 0; tt < TPI; tt++)
                    zv[tt] = fmaf(tD[tt][i], rd, zv[tt]);
            }
#pragma unroll
            for (int tt = 0; tt < TPI; tt++) {
                float z   = zv[tt];
                float arg = 0.7978845608028654f * fmaf(0.044715f*z, z*z, z);
                // 0.5*z*(1+tanh(arg)) == z / (1 + exp(-2*arg))
                zv[tt] = __fdividef(z, 1.0f + __expf(-2.0f * arg));
            }
#pragma unroll
            for (int i = 0; i < 4; i++) {
                float lu = pLuS[i*48 + 6*k + j];
#pragma unroll
                for (int tt = 0; tt < TPI; tt++)
                    s2[tt][i] = fmaf(zv[tt], lu, s2[tt][i]);
            }
        }
#pragma unroll
        for (int tt = 0; tt < TPI; tt++)
#pragma unroll
            for (int i = 0; i < 4; i++) {
                float v = s2[tt][i];
                v += __shfl_xor_sync(0xffffffffu, v, 4);
                v += __shfl_xor_sync(0xffffffffu, v, 2);
                v += __shfl_xor_sync(0xffffffffu, v, 1);
                s2[tt][i] = v;
            }

        // ---- up stage 2: tU[c][i] (c = g) ----
        float tU[TPI][4];
#pragma unroll
        for (int tt = 0; tt < TPI; tt++)
#pragma unroll
            for (int i = 0; i < 4; i++) tU[tt][i] = 0.f;
#pragma unroll
        for (int a = 0; a < 4; a++)
#pragma unroll
            for (int i = 0; i < 4; i++) {
                float r = sRu[i*16 + a*4 + g];
#pragma unroll
                for (int tt = 0; tt < TPI; tt++)
                    tU[tt][i] = fmaf(r, __shfl_sync(0xffffffffu, s2[tt][i], a*8),
                                     tU[tt][i]);
            }

        // ---- direct coalesced output (packed f32x2): f = l + 32j ----
#pragma unroll
        for (int j = 0; j < 6; j++) {
            const int f   = l + 32*j;
            const int c   = f / 48;
            const int src = c*8 + k;          // any lane of group c holds tU[c]
            const int q4  = f - c*48;
            ulonglong2 bb = __ldg(&bu2[f]);
            ulonglong2 rv[4];
#pragma unroll
            for (int i = 0; i < 4; i++) rv[i] = pRu2[i*48 + q4];
#pragma unroll
            for (int tt = 0; tt < TPI; tt++) {
                ulonglong2 o = bb;
#pragma unroll
                for (int i = 0; i < 4; i++) {
                    float tv = __shfl_sync(0xffffffffu, tU[tt][i], src);
                    u64 tvp = pk2(tv, tv);
                    o.x = fma2(tvp, rv[i].x, o.x);
                    o.y = fma2(tvp, rv[i].y, o.y);
                }
                if (base + tt < ntok)
                    o2[(size_t)(base + tt) * 192 + f] = o;
            }
        }
    }
}

extern "C" void kernel_launch(void* const* d_in, const int* in_sizes, int n_in,
                              void* d_out, int out_size)
{
    const float* x      = (const float*)d_in[0];
    const float* rule_d = (const float*)d_in[1];
    const float* Ld     = (const float*)d_in[2];
    const float* Rd     = (const float*)d_in[3];
    const float* bd     = (const float*)d_in[4];
    const float* rule_u = (const float*)d_in[5];
    const float* Lu     = (const float*)d_in[6];
    const float* Ru     = (const float*)d_in[7];
    const float* bu     = (const float*)d_in[8];

    const int ntok = in_sizes[0] / 768;

    cudaFuncSetAttribute(phm_fused_kernel,
                         cudaFuncAttributeMaxDynamicSharedMemorySize,
                         SMEM_TOTAL);

    // 148 SMs * 5 CTAs (128 thr, 44KB smem each) = one full wave
    phm_fused_kernel<<<740, NT, SMEM_TOTAL>>>(x, rule_d, Ld, Rd, bd,
                                              rule_u, Lu, Ru, bu,
                                              (float*)d_out, ntok);
}